// round 17
// baseline (speedup 1.0000x reference)
#include <cuda_runtime.h>
#include <cstdint>

// Problem constants
#define BATCH 4
#define CH    64
#define HH    64
#define WW    64
#define QHH   128
#define QWW   128
#define HID   256
#define OUT3  1728      // C*9*3
#define NK    576       // C*9
#define EPSV  1e-6f

// pw table, transposed: row k (576) x 12 floats [s0o0 s0o1 s0o2 s1o0 ... s3o2]
__device__ float g_pwT[NK * 12];

// ---------------------------------------------------------------------------
// Kernel A: MLP for the 4 parity classes -> g_pwT. Atomic-free, init-free.
// ---------------------------------------------------------------------------
__global__ void __launch_bounds__(256) mlp_pw_kernel(
    const float* __restrict__ coord, const float* __restrict__ cell,
    const float* __restrict__ w1,    const float* __restrict__ b1,
    const float* __restrict__ w2,    const float* __restrict__ b2)
{
    __shared__ float s_h[4][HID];        // hdd for the 4 parity classes
    __shared__ float s_part[16][16][4];  // [jsub][col][s]

    int tid = threadIdx.x;

    {
        int j = tid;
        #pragma unroll
        for (int s = 0; s < 4; ++s) {
            int py = s >> 1, px = s & 1;
            int qs = py * QWW + px;           // representative query (batch 0)
            float cy = coord[qs * 2 + 0];
            float cx = coord[qs * 2 + 1];
            float ly = cell[qs * 2 + 0];
            float lx = cell[qs * 2 + 1];
            float cy_ = cy - ly * 0.5f;
            float cx_ = cx - lx * 0.5f;
            float cqy = fminf(fmaxf(cy_ + EPSV, -1.0f + EPSV), 1.0f - EPSV);
            float cqx = fminf(fmaxf(cx_ + EPSV, -1.0f + EPSV), 1.0f - EPSV);
            float fy = ((cqy + 1.0f) * 64.0f - 1.0f) * 0.5f;
            float fx = ((cqx + 1.0f) * 64.0f - 1.0f) * 0.5f;
            float iy = fminf(fmaxf(rintf(fy), 0.0f), 63.0f);
            float ix = fminf(fmaxf(rintf(fx), 0.0f), 63.0f);
            float qcy = -1.0f + 2.0f * iy / 64.0f;
            float qcx = -1.0f + 2.0f * ix / 64.0f;
            float ry = (cy_ - qcy) * 32.0f;
            float rx = (cx_ - qcx) * 32.0f;
            float rr = ly * 32.0f;
            float h = ry * w1[j] + rx * w1[HID + j] + rr * w1[2 * HID + j] + b1[j];
            s_h[s][j] = fmaxf(h, 0.0f);
        }
    }
    __syncthreads();

    int col  = tid & 15;                        // 0..15
    int jsub = tid >> 4;                        // 0..15
    int k3   = blockIdx.x * 16 + col;           // 0..1727
    int j0   = jsub * 16;

    float a0 = 0.f, a1 = 0.f, a2 = 0.f, a3 = 0.f;
    const float* wp = w2 + (size_t)j0 * OUT3 + k3;
    #pragma unroll
    for (int j = 0; j < 16; ++j) {
        float w = wp[(size_t)j * OUT3];
        int jj = j0 + j;
        a0 = fmaf(s_h[0][jj], w, a0);
        a1 = fmaf(s_h[1][jj], w, a1);
        a2 = fmaf(s_h[2][jj], w, a2);
        a3 = fmaf(s_h[3][jj], w, a3);
    }
    s_part[jsub][col][0] = a0;
    s_part[jsub][col][1] = a1;
    s_part[jsub][col][2] = a2;
    s_part[jsub][col][3] = a3;
    __syncthreads();

    if (tid < 64) {
        int oc = tid >> 2;          // 0..15
        int os = tid & 3;           // 0..3
        int k3o = blockIdx.x * 16 + oc;
        float v = b2[k3o];
        #pragma unroll
        for (int t = 0; t < 16; ++t) v += s_part[t][oc][os];
        int k = k3o / 3;
        int o = k3o - k * 3;
        g_pwT[k * 12 + os * 3 + o] = v;
    }
}

// ---------------------------------------------------------------------------
// f32x2 packed helpers (FFMA2 — PTX-only on sm_10x)
// ---------------------------------------------------------------------------
__device__ __forceinline__ void ffma2(unsigned long long& d,
                                      unsigned long long a,
                                      unsigned long long b)
{
    asm("fma.rn.f32x2 %0, %1, %2, %0;" : "+l"(d) : "l"(a), "l"(b));
}
__device__ __forceinline__ void addf2(unsigned long long& d, unsigned long long a)
{
    asm("add.rn.f32x2 %0, %0, %1;" : "+l"(d) : "l"(a));
}

// ---------------------------------------------------------------------------
// Kernel B: 2 px/lane, 8 warps/SMSP, ZERO spills, duplicated-pair feat tile.
// grid = 256, block = 512 (16 warps), 2 blocks/SM -> 32 warps/SM.
// Block = 2 LR rows x 32 cols (64 px); k (576) split 16 warps x 4 channels.
// Lane owns (row0,col=lane) & (row1,col=lane) -> 12 f32x2 accumulators.
// Feat tile stored as duplicated (f,f) float2 pairs: feat operand = one
// LDS.64, no packing movs. Live set ~55 regs -> fits 64-reg budget.
// smem = 97.2KB -> 2 blocks/SM (194.5KB <= 228KB).
// ---------------------------------------------------------------------------
#define TW3   34
#define NROWS 4
#define CS2   (NROWS * TW3)             // 136 float2 per channel
#define TILE2_WORDS (CH * CS2 * 2)      // 17408 floats (69632 B)
#define PW_WORDS    (NK * 12)           // 6912 floats  (27648 B)
#define SMEM_B ((TILE2_WORDS + PW_WORDS) * 4)   // 97280 bytes

__global__ void __launch_bounds__(512, 2) metasr_main_kernel(
    const float* __restrict__ feat, float* __restrict__ out)
{
    extern __shared__ float smem[];
    float2* s_tile2 = (float2*)smem;            // [64][4][34] duplicated pairs
    float*  s_pw    = smem + TILE2_WORDS;       // [576][12]

    int tid = threadIdx.x;
    int bx  = blockIdx.x;                  // 0..255
    int b   = bx >> 6;
    int y0  = ((bx >> 1) & 31) * 2;        // first of 2 LR rows
    int x0  = (bx & 1) * 32;               // column half

    const float* fb = feat + (size_t)b * CH * HH * WW;

    // ---- feat tile first (overlaps kernel A via PDL) ----
    // halo columns: tile col 0 (gx = x0-1) and col 33 (gx = x0+32)
    {
        int i = tid;                                   // 512 -> exactly 1
        int c    = i >> 3;
        int rr   = (i >> 1) & 3;
        int side = i & 1;
        int gy   = y0 - 1 + rr;
        int gx   = x0 - 1 + side * 33;
        float v = 0.0f;
        if ((unsigned)gy < 64u && (unsigned)gx < 64u)
            v = fb[((c << 6) + gy) * 64 + gx];
        s_tile2[c * CS2 + rr * TW3 + side * 33] = make_float2(v, v);
    }

    // interior: 32 cols per row via float4 loads, stored duplicated
    #pragma unroll
    for (int it = 0; it < 4; ++it) {                   // 2048 total
        int i   = it * 512 + tid;
        int c   = i >> 5;
        int rr  = (i >> 3) & 3;
        int q   = i & 7;
        int gy  = y0 - 1 + rr;
        float4 v = make_float4(0.f, 0.f, 0.f, 0.f);
        if ((unsigned)gy < 64u)
            v = *(const float4*)(fb + ((c << 6) + gy) * 64 + x0 + q * 4);
        float2* dst = s_tile2 + c * CS2 + rr * TW3 + 1 + q * 4;
        dst[0] = make_float2(v.x, v.x);
        dst[1] = make_float2(v.y, v.y);
        dst[2] = make_float2(v.z, v.z);
        dst[3] = make_float2(v.w, v.w);
    }

    // ---- wait for kernel A's g_pwT, then load it ----
    cudaGridDependencySynchronize();
    {
        const float4* src = (const float4*)g_pwT;
        float4* dst = (float4*)s_pw;
        for (int i = tid; i < PW_WORDS / 4; i += 512) dst[i] = src[i];
    }
    __syncthreads();

    // ---- main loop: warp w owns channels [4w, 4w+4) ----
    int w    = tid >> 5;
    int lane = tid & 31;

    const unsigned long long* tw4 =
        (const unsigned long long*)s_tile2 + (w << 2) * CS2 + lane;
    const ulonglong2* pk0 = (const ulonglong2*)s_pw + (w * 36) * 3;

    unsigned long long acc[12];
    #pragma unroll
    for (int i = 0; i < 12; ++i) acc[i] = 0ull;

    #pragma unroll
    for (int g = 0; g < 12; ++g) {            // group = (cc, dx)
        const int cc = g / 3, dx = g % 3;

        // 4-row feat column (rows shared by the 2 pixel rows), direct LDS.64
        unsigned long long R0 = tw4[cc * CS2 + 0 * TW3 + dx];
        unsigned long long R1 = tw4[cc * CS2 + 1 * TW3 + dx];
        unsigned long long R2 = tw4[cc * CS2 + 2 * TW3 + dx];
        unsigned long long R3 = tw4[cc * CS2 + 3 * TW3 + dx];

        #pragma unroll
        for (int dy = 0; dy < 3; ++dy) {
            const ulonglong2* p = pk0 + cc * 27 + (dy * 3 + dx) * 3;
            ulonglong2 p01 = p[0];
            ulonglong2 p23 = p[1];
            ulonglong2 p45 = p[2];
            unsigned long long F0 = (dy == 0) ? R0 : (dy == 1) ? R1 : R2;
            unsigned long long F1 = (dy == 0) ? R1 : (dy == 1) ? R2 : R3;
            ffma2(acc[0],  F0, p01.x); ffma2(acc[1],  F0, p01.y);
            ffma2(acc[2],  F0, p23.x); ffma2(acc[3],  F0, p23.y);
            ffma2(acc[4],  F0, p45.x); ffma2(acc[5],  F0, p45.y);
            ffma2(acc[6],  F1, p01.x); ffma2(acc[7],  F1, p01.y);
            ffma2(acc[8],  F1, p23.x); ffma2(acc[9],  F1, p23.y);
            ffma2(acc[10], F1, p45.x); ffma2(acc[11], F1, p45.y);
        }
    }

    // ---- cross-warp reduction: s_red[w(16)][a(12)][33] padded ull ----
    __syncthreads();
    unsigned long long* s_red = (unsigned long long*)smem;
    #pragma unroll
    for (int a = 0; a < 12; ++a)
        s_red[(w * 12 + a) * 33 + lane] = acc[a];
    __syncthreads();

    // pass 2: 384 output ull = (r 2) x (col 32) x (a 6); 2x8-way reduce
    if (tid < 384) {
        int r   = tid / 192;
        int rem = tid - r * 192;
        int col = rem / 6;
        int a   = rem - col * 6;

        int srcidx = r * 6 + a;
        unsigned long long v0 = s_red[srcidx * 33 + col];
        unsigned long long v1 = s_red[(8 * 12 + srcidx) * 33 + col];
        #pragma unroll
        for (int ww = 1; ww < 8; ++ww) {
            addf2(v0, s_red[(ww * 12 + srcidx) * 33 + col]);
            addf2(v1, s_red[((ww + 8) * 12 + srcidx) * 33 + col]);
        }
        addf2(v0, v1);

        int yq = 2 * (y0 + r) + (a / 3);     // a 0-2 -> HR row 2y, 3-5 -> 2y+1
        int xq = 2 * (x0 + col);
        int jj = a % 3;
        size_t base = ((size_t)(b * QHH + yq) * QWW + xq) * 3 + jj * 2;
        *(unsigned long long*)(out + base) = v0;
    }
}

// ---------------------------------------------------------------------------
extern "C" void kernel_launch(void* const* d_in, const int* in_sizes, int n_in,
                              void* d_out, int out_size)
{
    const float* feat  = (const float*)d_in[0];
    const float* coord = (const float*)d_in[1];
    const float* cell  = (const float*)d_in[2];
    const float* w1    = (const float*)d_in[3];
    const float* b1    = (const float*)d_in[4];
    const float* w2    = (const float*)d_in[5];
    const float* b2    = (const float*)d_in[6];
    float* out = (float*)d_out;

    cudaFuncSetAttribute(metasr_main_kernel,
                         cudaFuncAttributeMaxDynamicSharedMemorySize, SMEM_B);

    mlp_pw_kernel<<<108, 256>>>(coord, cell, w1, b1, w2, b2);

    // Main kernel with Programmatic Dependent Launch: starts while kernel A
    // runs, loads its feat tile, then grid-dep-syncs before reading g_pwT.
    cudaLaunchConfig_t cfg = {};
    cfg.gridDim  = dim3(256, 1, 1);
    cfg.blockDim = dim3(512, 1, 1);
    cfg.dynamicSmemBytes = SMEM_B;
    cfg.stream = 0;
    cudaLaunchAttribute attrs[1];
    attrs[0].id = cudaLaunchAttributeProgrammaticStreamSerialization;
    attrs[0].val.programmaticStreamSerializationAllowed = 1;
    cfg.attrs = attrs;
    cfg.numAttrs = 1;
    cudaLaunchKernelEx(&cfg, metasr_main_kernel, feat, out);
}